// round 1
// baseline (speedup 1.0000x reference)
#include <cuda_runtime.h>
#include <cstdint>

// Fixed problem geometry: x_list (P=16384, N=1024, 2) float32, scale scalar.
// segn = N/4 = 256 segments per row; segment i uses points 3i..3i+3.
#define N_POINTS   1024
#define SEGN       256
#define MAX_ROWS   16384

__device__ float g_partials[MAX_ROWS];

__global__ void __launch_bounds__(SEGN) xing_partial_kernel(
    const float* __restrict__ x, int P)
{
    const int row = blockIdx.x;
    const int t   = threadIdx.x;            // segment index 0..255

    // Row base as float2 (points); segment i starts at point 3i.
    const float2* __restrict__ p =
        reinterpret_cast<const float2*>(x) + (size_t)row * N_POINTS + 3 * t;

    const float2 p0 = __ldg(p + 0);
    const float2 p1 = __ldg(p + 1);
    const float2 p2 = __ldg(p + 2);
    const float2 p3 = __ldg(p + 3);

    const float v1x = p1.x - p0.x, v1y = p1.y - p0.y;
    const float v2x = p2.x - p1.x, v2y = p2.y - p1.y;
    const float v3x = p3.x - p2.x, v3y = p3.y - p2.y;

    // direct = (s12 >= 0) depends only on the sign of cross(v1, v2):
    const float c12 = v1x * v2y - v1y * v2x;
    const float c13 = v1x * v3y - v1y * v3x;

    const float n2  = (v1x * v1x + v1y * v1y) * (v3x * v3x + v3y * v3y);
    const float sina = c13 * rsqrtf(n2);

    // direct -> relu(-sina); else relu(sina)
    float term = (c12 >= 0.0f) ? fmaxf(-sina, 0.0f) : fmaxf(sina, 0.0f);

    // warp reduce
    #pragma unroll
    for (int o = 16; o > 0; o >>= 1)
        term += __shfl_down_sync(0xFFFFFFFFu, term, o);

    __shared__ float s[SEGN / 32];
    if ((t & 31) == 0) s[t >> 5] = term;
    __syncthreads();

    if (t < SEGN / 32) {
        float v = s[t];
        #pragma unroll
        for (int o = (SEGN / 64); o > 0; o >>= 1)
            v += __shfl_down_sync(0xFFu, v, o);
        if (t == 0) g_partials[row] = v;
    }
}

__global__ void __launch_bounds__(1024) xing_final_kernel(
    const uint32_t* __restrict__ scale_raw, float* __restrict__ out, int P)
{
    const int tid = threadIdx.x;
    float acc = 0.0f;
    for (int i = tid; i < P; i += blockDim.x)
        acc += g_partials[i];

    #pragma unroll
    for (int o = 16; o > 0; o >>= 1)
        acc += __shfl_down_sync(0xFFFFFFFFu, acc, o);

    __shared__ float s[32];
    if ((tid & 31) == 0) s[tid >> 5] = acc;
    __syncthreads();

    if (tid < 32) {
        float v = (tid < (int)(blockDim.x >> 5)) ? s[tid] : 0.0f;
        #pragma unroll
        for (int o = 16; o > 0; o >>= 1)
            v += __shfl_down_sync(0xFFFFFFFFu, v, o);
        if (tid == 0) {
            // Decode scale: float32 bit pattern vs (small) integer bit pattern.
            uint32_t u = scale_raw[0];
            float f = __uint_as_float(u);
            float scale;
            if (fabsf(f) >= 1e-30f && fabsf(f) < 1e30f) scale = f;       // float32
            else                                        scale = (float)(int)u; // int32/int64 low word
            out[0] = v * scale / ((float)SEGN * (float)P);
        }
    }
}

extern "C" void kernel_launch(void* const* d_in, const int* in_sizes, int n_in,
                              void* d_out, int out_size)
{
    const float*    x     = (const float*)d_in[0];
    const uint32_t* scale = (const uint32_t*)d_in[1];
    float*          out   = (float*)d_out;

    // P from element count: in_sizes[0] = P * N_POINTS * 2
    int P = in_sizes[0] / (N_POINTS * 2);
    if (P > MAX_ROWS) P = MAX_ROWS;

    xing_partial_kernel<<<P, SEGN>>>(x, P);
    xing_final_kernel<<<1, 1024>>>(scale, out, P);
}